// round 1
// baseline (speedup 1.0000x reference)
#include <cuda_runtime.h>
#include <cuda_bf16.h>
#include <cstdint>

#define BB    8
#define NN    896
#define MM    512
#define KSEQ  3072
#define KAA   1280
#define HN    32
#define DD    64
#define INNER 2048
#define CTXD  256

// ---------------- scratch (no allocations allowed -> __device__ globals) ----
__device__ __nv_bfloat16 g_seq_lat[(size_t)BB * HN * NN * DD];   // 28 MiB
__device__ __nv_bfloat16 g_aa_lat[(size_t)BB * HN * MM * DD];    // 16 MiB
__device__ float g_lse[(size_t)BB * NN * HN];                    // [b][i][h]
__device__ float g_maskf[BB * MM];                               // 1 = keep, 0 = masked
__device__ float g_v[BB * HN];

// ---------------- small PTX helpers ----------------------------------------
__device__ __forceinline__ uint32_t sptr(const void* p) {
    return (uint32_t)__cvta_generic_to_shared(const_cast<void*>(p));
}
__device__ __forceinline__ void ldsm_x4(uint32_t* r, uint32_t addr) {
    asm volatile("ldmatrix.sync.aligned.m8n8.x4.shared.b16 {%0,%1,%2,%3}, [%4];\n"
                 : "=r"(r[0]), "=r"(r[1]), "=r"(r[2]), "=r"(r[3]) : "r"(addr));
}
__device__ __forceinline__ void mma_bf16(float* c, const uint32_t* a, const uint32_t* b) {
    asm volatile(
        "mma.sync.aligned.m16n8k16.row.col.f32.bf16.bf16.f32 "
        "{%0,%1,%2,%3}, {%4,%5,%6,%7}, {%8,%9}, {%0,%1,%2,%3};\n"
        : "+f"(c[0]), "+f"(c[1]), "+f"(c[2]), "+f"(c[3])
        : "r"(a[0]), "r"(a[1]), "r"(a[2]), "r"(a[3]), "r"(b[0]), "r"(b[1]));
}

// ---------------- mask dtype detection + float expansion --------------------
// jax bool may arrive as uint8, int32, or float32. Detect from byte pattern.
__global__ void mask_init_kernel(const unsigned char* __restrict__ mraw) {
    __shared__ int u8f, f32f;
    if (threadIdx.x == 0) { u8f = 0; f32f = 0; }
    __syncthreads();
    for (int i = threadIdx.x; i < BB * MM; i += blockDim.x) {   // first 4096 bytes: safe for all dtypes
        unsigned char v = mraw[i];
        if ((i & 3) != 0 && v != 0) atomicOr(&u8f, 1);
        if ((i & 3) == 3 && v == 0x3f) atomicOr(&f32f, 1);      // 1.0f high byte
    }
    __syncthreads();
    int mode = f32f ? 2 : (u8f ? 0 : 1);   // 0=u8, 1=i32, 2=f32
    for (int i = threadIdx.x; i < BB * MM; i += blockDim.x) {
        bool msk;
        if (mode == 0)      msk = mraw[i] != 0;
        else if (mode == 1) msk = ((const int*)mraw)[i] != 0;
        else                msk = ((const float*)mraw)[i] != 0.0f;
        g_maskf[i] = msk ? 0.0f : 1.0f;
    }
}

// ---------------- projection GEMM + bias + per-head l2norm ------------------
// C[M x 2048] = A[M x K] * W[K x 2048] + bias, then l2norm over 64-wide head
// groups, store bf16 to out[b][h][i][d].   Tiles: BM=128, BN=128, BK=32.
// 8 warps as 4(m) x 2(n): warp tile 32 x 64 => each warp owns a full head group.
__global__ __launch_bounds__(256) void proj_norm_kernel(
    const float* __restrict__ A, const float* __restrict__ W,
    const float* __restrict__ bias, int K, int rowsPerB, int isSeq)
{
    __nv_bfloat16* __restrict__ out = isSeq ? g_seq_lat : g_aa_lat;
    const int tid  = threadIdx.x;
    const int lane = tid & 31;
    const int w    = tid >> 5;
    const int wm   = w & 3;
    const int wn   = w >> 2;
    const int rowBase = blockIdx.y * 128;
    const int colBase = blockIdx.x * 128;

    __shared__ __nv_bfloat16 sA[2][128][40];   // [m][k], pad 40 (80B rows, ldmatrix-clean)
    __shared__ __nv_bfloat16 sB[2][128][40];   // [n][k]

    float4 ra[4], rb[4];
    float acc[2][8][4];
#pragma unroll
    for (int mi = 0; mi < 2; mi++)
#pragma unroll
        for (int ni = 0; ni < 8; ni++)
#pragma unroll
            for (int q = 0; q < 4; q++) acc[mi][ni][q] = 0.f;

    const int KT = K >> 5;
    // prologue: load k-tile 0
    {
        const float* Ap = A + (size_t)(rowBase + (tid >> 3)) * K + (tid & 7) * 4;
#pragma unroll
        for (int i = 0; i < 4; i++) ra[i] = *(const float4*)(Ap + (size_t)32 * i * K);
        const float* Wp = W + (size_t)(tid >> 5) * INNER + colBase + (tid & 31) * 4;
#pragma unroll
        for (int i = 0; i < 4; i++) rb[i] = *(const float4*)(Wp + (size_t)8 * i * INNER);
    }
    // store tile 0 to buf 0
    {
#pragma unroll
        for (int i = 0; i < 4; i++) {
            int row = (tid >> 3) + 32 * i, kq = tid & 7;
            __nv_bfloat162* p = (__nv_bfloat162*)&sA[0][row][kq * 4];
            p[0] = __floats2bfloat162_rn(ra[i].x, ra[i].y);
            p[1] = __floats2bfloat162_rn(ra[i].z, ra[i].w);
        }
#pragma unroll
        for (int i = 0; i < 4; i++) {
            int kk = (tid >> 5) + 8 * i, nq = tid & 31;
            sB[0][nq * 4 + 0][kk] = __float2bfloat16_rn(rb[i].x);
            sB[0][nq * 4 + 1][kk] = __float2bfloat16_rn(rb[i].y);
            sB[0][nq * 4 + 2][kk] = __float2bfloat16_rn(rb[i].z);
            sB[0][nq * 4 + 3][kk] = __float2bfloat16_rn(rb[i].w);
        }
    }
    __syncthreads();

    for (int kt = 0; kt < KT; kt++) {
        const int buf = kt & 1;
        if (kt + 1 < KT) {   // prefetch next tile into regs
            const float* Ap = A + (size_t)(rowBase + (tid >> 3)) * K + (kt + 1) * 32 + (tid & 7) * 4;
#pragma unroll
            for (int i = 0; i < 4; i++) ra[i] = *(const float4*)(Ap + (size_t)32 * i * K);
            const float* Wp = W + (size_t)((kt + 1) * 32 + (tid >> 5)) * INNER + colBase + (tid & 31) * 4;
#pragma unroll
            for (int i = 0; i < 4; i++) rb[i] = *(const float4*)(Wp + (size_t)8 * i * INNER);
        }
#pragma unroll
        for (int ks = 0; ks < 2; ks++) {
            uint32_t af[2][4];
#pragma unroll
            for (int mi = 0; mi < 2; mi++)
                ldsm_x4(af[mi], sptr(&sA[buf][wm * 32 + mi * 16 + (lane & 15)][ks * 16 + ((lane >> 4) << 3)]));
            uint32_t bfr[8][2];
#pragma unroll
            for (int nb = 0; nb < 4; nb++) {
                uint32_t r[4];
                ldsm_x4(r, sptr(&sB[buf][wn * 64 + nb * 16 + (lane & 15)][ks * 16 + ((lane >> 4) << 3)]));
                bfr[2 * nb][0] = r[0];     bfr[2 * nb][1] = r[2];
                bfr[2 * nb + 1][0] = r[1]; bfr[2 * nb + 1][1] = r[3];
            }
#pragma unroll
            for (int mi = 0; mi < 2; mi++)
#pragma unroll
                for (int ni = 0; ni < 8; ni++) mma_bf16(acc[mi][ni], af[mi], bfr[ni]);
        }
        if (kt + 1 < KT) {
            const int nbuf = buf ^ 1;
#pragma unroll
            for (int i = 0; i < 4; i++) {
                int row = (tid >> 3) + 32 * i, kq = tid & 7;
                __nv_bfloat162* p = (__nv_bfloat162*)&sA[nbuf][row][kq * 4];
                p[0] = __floats2bfloat162_rn(ra[i].x, ra[i].y);
                p[1] = __floats2bfloat162_rn(ra[i].z, ra[i].w);
            }
#pragma unroll
            for (int i = 0; i < 4; i++) {
                int kk = (tid >> 5) + 8 * i, nq = tid & 31;
                sB[nbuf][nq * 4 + 0][kk] = __float2bfloat16_rn(rb[i].x);
                sB[nbuf][nq * 4 + 1][kk] = __float2bfloat16_rn(rb[i].y);
                sB[nbuf][nq * 4 + 2][kk] = __float2bfloat16_rn(rb[i].z);
                sB[nbuf][nq * 4 + 3][kk] = __float2bfloat16_rn(rb[i].w);
            }
        }
        __syncthreads();
    }

    // epilogue: bias + l2norm over this warp's 64-wide head group, store bf16
    const int h     = (colBase >> 6) + wn;
    const int bI    = rowBase / rowsPerB;            // tiles never straddle b (128 | rowsPerB)
    const int iBase = rowBase - bI * rowsPerB;
    const float* bptr = bias + colBase + wn * 64;
#pragma unroll
    for (int mi = 0; mi < 2; mi++) {
        float slo = 0.f, shi = 0.f;
#pragma unroll
        for (int ni = 0; ni < 8; ni++) {
            int c0 = ni * 8 + 2 * (lane & 3);
            float b0 = bptr[c0], b1 = bptr[c0 + 1];
            acc[mi][ni][0] += b0; acc[mi][ni][1] += b1;
            acc[mi][ni][2] += b0; acc[mi][ni][3] += b1;
            slo += acc[mi][ni][0] * acc[mi][ni][0] + acc[mi][ni][1] * acc[mi][ni][1];
            shi += acc[mi][ni][2] * acc[mi][ni][2] + acc[mi][ni][3] * acc[mi][ni][3];
        }
        slo += __shfl_xor_sync(0xffffffffu, slo, 1);
        slo += __shfl_xor_sync(0xffffffffu, slo, 2);
        shi += __shfl_xor_sync(0xffffffffu, shi, 1);
        shi += __shfl_xor_sync(0xffffffffu, shi, 2);
        float scl = rsqrtf(fmaxf(slo, 1e-24f));
        float sch = rsqrtf(fmaxf(shi, 1e-24f));
        int rw = wm * 32 + mi * 16 + (lane >> 2);
        __nv_bfloat16* op = out + (((size_t)bI * HN + h) * rowsPerB + iBase + rw) * DD;
#pragma unroll
        for (int ni = 0; ni < 8; ni++) {
            int d = ni * 8 + 2 * (lane & 3);
            *(__nv_bfloat162*)(op + d) =
                __floats2bfloat162_rn(acc[mi][ni][0] * scl, acc[mi][ni][1] * scl);
            *(__nv_bfloat162*)(op + 8 * DD + d) =
                __floats2bfloat162_rn(acc[mi][ni][2] * sch, acc[mi][ni][3] * sch);
        }
    }
}

// ---------------- fused cosine-sim GEMM + masked sum-exp --------------------
// Per (b,h): S = Q[896x64] * K[512x64]^T; sims in [-1,1] so logsumexp needs no
// max pass: lse = log(sum_j exp(S_ij) * maskf_j). Block = 64 i-rows, loops
// 4 j-chunks of 128. 8 warps as 2(m) x 4(n), warp tile 32x32.
__global__ __launch_bounds__(256) void sims_lse_kernel()
{
    const int bh = blockIdx.x;
    const int b = bh >> 5, h = bh & 31;
    const int it = blockIdx.y;
    const int tid = threadIdx.x, lane = tid & 31, w = tid >> 5;
    const int wm = w >> 2;   // 0..1
    const int wn = w & 3;    // 0..3

    __shared__ __nv_bfloat16 sQ[64][72];
    __shared__ __nv_bfloat16 sK[128][72];
    __shared__ float sMask[128];
    __shared__ float rowpart[4][64];
    __shared__ float rowacc[64];

    {   // Q tile once
        const uint4* src = (const uint4*)(g_seq_lat + (((size_t)(b * HN + h)) * NN + it * 64) * DD);
        for (int i = tid; i < 512; i += 256) {
            int r = i >> 3, q = i & 7;
            *(uint4*)&sQ[r][q * 8] = src[i];
        }
    }
    if (tid < 64) rowacc[tid] = 0.f;
    __syncthreads();

    const __nv_bfloat16* kbase = g_aa_lat + ((size_t)(b * HN + h)) * MM * DD;
    for (int jc = 0; jc < 4; jc++) {
        const uint4* ksrc = (const uint4*)(kbase + (size_t)jc * 128 * DD);
        for (int i = tid; i < 1024; i += 256) {
            int r = i >> 3, q = i & 7;
            *(uint4*)&sK[r][q * 8] = ksrc[i];
        }
        if (tid < 128) sMask[tid] = g_maskf[b * MM + jc * 128 + tid];
        __syncthreads();

        float acc[2][4][4];
#pragma unroll
        for (int mi = 0; mi < 2; mi++)
#pragma unroll
            for (int ni = 0; ni < 4; ni++)
#pragma unroll
                for (int q = 0; q < 4; q++) acc[mi][ni][q] = 0.f;

#pragma unroll
        for (int ks = 0; ks < 4; ks++) {
            uint32_t af[2][4];
#pragma unroll
            for (int mi = 0; mi < 2; mi++)
                ldsm_x4(af[mi], sptr(&sQ[wm * 32 + mi * 16 + (lane & 15)][ks * 16 + ((lane >> 4) << 3)]));
            uint32_t bfr[4][2];
#pragma unroll
            for (int nb = 0; nb < 2; nb++) {
                uint32_t r[4];
                ldsm_x4(r, sptr(&sK[wn * 32 + nb * 16 + (lane & 15)][ks * 16 + ((lane >> 4) << 3)]));
                bfr[2 * nb][0] = r[0];     bfr[2 * nb][1] = r[2];
                bfr[2 * nb + 1][0] = r[1]; bfr[2 * nb + 1][1] = r[3];
            }
#pragma unroll
            for (int mi = 0; mi < 2; mi++)
#pragma unroll
                for (int ni = 0; ni < 4; ni++) mma_bf16(acc[mi][ni], af[mi], bfr[ni]);
        }

        // exp + mask + per-row partial sums
#pragma unroll
        for (int mi = 0; mi < 2; mi++) {
            float pl = 0.f, ph = 0.f;
#pragma unroll
            for (int ni = 0; ni < 4; ni++) {
                int c = wn * 32 + ni * 8 + 2 * (lane & 3);
                float m0 = sMask[c], m1 = sMask[c + 1];
                pl += __expf(acc[mi][ni][0]) * m0 + __expf(acc[mi][ni][1]) * m1;
                ph += __expf(acc[mi][ni][2]) * m0 + __expf(acc[mi][ni][3]) * m1;
            }
            pl += __shfl_xor_sync(0xffffffffu, pl, 1);
            pl += __shfl_xor_sync(0xffffffffu, pl, 2);
            ph += __shfl_xor_sync(0xffffffffu, ph, 1);
            ph += __shfl_xor_sync(0xffffffffu, ph, 2);
            if ((lane & 3) == 0) {
                int r = wm * 32 + mi * 16 + (lane >> 2);
                rowpart[wn][r] = pl;
                rowpart[wn][r + 8] = ph;
            }
        }
        __syncthreads();
        if (tid < 64)
            rowacc[tid] += rowpart[0][tid] + rowpart[1][tid] + rowpart[2][tid] + rowpart[3][tid];
        __syncthreads();
    }
    if (tid < 64) {
        int i = it * 64 + tid;
        g_lse[((size_t)b * NN + i) * HN + h] = logf(rowacc[tid]);
    }
}

// ---------------- gating -> collapsed mixing vector v[b][h] -----------------
// v[b,h] = sum_e to_logits_w[h,e] * sigmoid(ctx[b]@ctx_w[:,h*32+e]+ctx_b) * pred_w[e]
__global__ void gating_kernel(const float* __restrict__ ctx, const float* __restrict__ ctx_w,
                              const float* __restrict__ ctx_b, const float* __restrict__ tw,
                              const float* __restrict__ pw)
{
    int b = blockIdx.x, t = threadIdx.x;
    __shared__ float sctx[CTXD];
    __shared__ float sgate[HN * HN];
    sctx[t] = ctx[b * CTXD + t];
    __syncthreads();
    for (int e = t; e < HN * HN; e += 256) {
        float s = ctx_b[e];
        for (int c = 0; c < CTXD; c++) s += sctx[c] * ctx_w[c * (HN * HN) + e];
        sgate[e] = 1.f / (1.f + __expf(-s));
    }
    __syncthreads();
    if (t < HN) {
        float v = 0.f;
#pragma unroll
        for (int e = 0; e < HN; e++) v += tw[t * HN + e] * sgate[t * HN + e] * pw[e];
        g_v[b * HN + t] = v;
    }
}

// ---------------- final: pred = softplus(lse . v + pred_b) ------------------
__global__ void pred_kernel(const float* __restrict__ pred_b, float* __restrict__ out)
{
    int idx = blockIdx.x * 256 + threadIdx.x;   // 0..7167
    int b = idx / NN;
    const float4* p = (const float4*)&g_lse[(size_t)idx * HN];
    const float* v = &g_v[b * HN];
    float x = pred_b[0];
#pragma unroll
    for (int q = 0; q < 8; q++) {
        float4 l = p[q];
        x += l.x * v[4 * q] + l.y * v[4 * q + 1] + l.z * v[4 * q + 2] + l.w * v[4 * q + 3];
    }
    out[idx] = fmaxf(x, 0.f) + log1pf(__expf(-fabsf(x)));
}

// ---------------- launcher ---------------------------------------------------
extern "C" void kernel_launch(void* const* d_in, const int* in_sizes, int n_in,
                              void* d_out, int out_size)
{
    const float* seq_embed = (const float*)d_in[0];
    const float* aa_embed  = (const float*)d_in[1];
    const float* ctx       = (const float*)d_in[2];
    const float* seq_w     = (const float*)d_in[3];
    const float* seq_b     = (const float*)d_in[4];
    const float* aa_w      = (const float*)d_in[5];
    const float* aa_b      = (const float*)d_in[6];
    const float* tw        = (const float*)d_in[7];
    const float* ctx_w     = (const float*)d_in[8];
    const float* ctx_b     = (const float*)d_in[9];
    const float* pw        = (const float*)d_in[10];
    const float* pb        = (const float*)d_in[11];
    const unsigned char* mask = (const unsigned char*)d_in[12];
    float* out = (float*)d_out;

    mask_init_kernel<<<1, 256>>>(mask);
    proj_norm_kernel<<<dim3(INNER / 128, (BB * NN) / 128), 256>>>(seq_embed, seq_w, seq_b, KSEQ, NN, 1);
    proj_norm_kernel<<<dim3(INNER / 128, (BB * MM) / 128), 256>>>(aa_embed, aa_w, aa_b, KAA, MM, 0);
    sims_lse_kernel<<<dim3(BB * HN, NN / 64), 256>>>();
    gating_kernel<<<BB, 256>>>(ctx, ctx_w, ctx_b, tw, pw);
    pred_kernel<<<(BB * NN) / 256, 256>>>(pb, out);
}

// round 4
// speedup vs baseline: 2.7232x; 2.7232x over previous
#include <cuda_runtime.h>
#include <cuda_bf16.h>
#include <cstdint>

#define BB    8
#define NN    896
#define MM    512
#define KSEQ  3072
#define KAA   1280
#define HN    32
#define DD    64
#define INNER 2048
#define CTXD  256

// ---------------- scratch (no allocations allowed -> __device__ globals) ----
__device__ __nv_bfloat16 g_seq_lat[(size_t)BB * HN * NN * DD];   // 28 MiB
__device__ __nv_bfloat16 g_aa_lat[(size_t)BB * HN * MM * DD];    // 16 MiB
__device__ float g_lse[(size_t)BB * NN * HN];                    // [b][i][h]
__device__ float g_maskf[BB * MM];                               // 1 = keep, 0 = masked
__device__ float g_v[BB * HN];
// bf16 prepass buffers
__device__ __nv_bfloat16 g_seq_bf[(size_t)BB * NN * KSEQ];       // 44 MiB  [row][k]
__device__ __nv_bfloat16 g_aa_bf[(size_t)BB * MM * KAA];         // 10.5 MiB
__device__ __nv_bfloat16 g_wseq_t[(size_t)INNER * KSEQ];         // 12.6 MiB [col][k]
__device__ __nv_bfloat16 g_waa_t[(size_t)INNER * KAA];           // 5.2 MiB

// ---------------- PTX helpers -----------------------------------------------
__device__ __forceinline__ uint32_t sptr(const void* p) {
    return (uint32_t)__cvta_generic_to_shared(const_cast<void*>(p));
}
__device__ __forceinline__ void ldsm_x4(uint32_t* r, uint32_t addr) {
    asm volatile("ldmatrix.sync.aligned.m8n8.x4.shared.b16 {%0,%1,%2,%3}, [%4];\n"
                 : "=r"(r[0]), "=r"(r[1]), "=r"(r[2]), "=r"(r[3]) : "r"(addr));
}
__device__ __forceinline__ void mma_bf16(float* c, const uint32_t* a, const uint32_t* b) {
    asm volatile(
        "mma.sync.aligned.m16n8k16.row.col.f32.bf16.bf16.f32 "
        "{%0,%1,%2,%3}, {%4,%5,%6,%7}, {%8,%9}, {%0,%1,%2,%3};\n"
        : "+f"(c[0]), "+f"(c[1]), "+f"(c[2]), "+f"(c[3])
        : "r"(a[0]), "r"(a[1]), "r"(a[2]), "r"(a[3]), "r"(b[0]), "r"(b[1]));
}
__device__ __forceinline__ void cp_async16(uint32_t dst, const void* src) {
    asm volatile("cp.async.cg.shared.global [%0], [%1], 16;\n" :: "r"(dst), "l"(src));
}
#define CP_COMMIT()  asm volatile("cp.async.commit_group;\n" ::: "memory")

// ---------------- mask dtype detection + float expansion --------------------
__global__ void mask_init_kernel(const unsigned char* __restrict__ mraw) {
    __shared__ int u8f, f32f;
    if (threadIdx.x == 0) { u8f = 0; f32f = 0; }
    __syncthreads();
    for (int i = threadIdx.x; i < BB * MM; i += blockDim.x) {
        unsigned char v = mraw[i];
        if ((i & 3) != 0 && v != 0) atomicOr(&u8f, 1);
        if ((i & 3) == 3 && v == 0x3f) atomicOr(&f32f, 1);
    }
    __syncthreads();
    int mode = f32f ? 2 : (u8f ? 0 : 1);
    for (int i = threadIdx.x; i < BB * MM; i += blockDim.x) {
        bool msk;
        if (mode == 0)      msk = mraw[i] != 0;
        else if (mode == 1) msk = ((const int*)mraw)[i] != 0;
        else                msk = ((const float*)mraw)[i] != 0.0f;
        g_maskf[i] = msk ? 0.0f : 1.0f;
    }
}

// ---------------- prepass: fp32 -> bf16 elementwise -------------------------
__global__ void to_bf16_kernel(const float* __restrict__ in, __nv_bfloat16* __restrict__ out, int n8) {
    int i = blockIdx.x * 256 + threadIdx.x;
    if (i >= n8) return;
    float4 a = ((const float4*)in)[2 * i];
    float4 b = ((const float4*)in)[2 * i + 1];
    __nv_bfloat162 o[4];
    o[0] = __floats2bfloat162_rn(a.x, a.y);
    o[1] = __floats2bfloat162_rn(a.z, a.w);
    o[2] = __floats2bfloat162_rn(b.x, b.y);
    o[3] = __floats2bfloat162_rn(b.z, b.w);
    ((uint4*)out)[i] = *(uint4*)o;
}

// ---------------- prepass: W[K][2048] fp32 -> Wt[2048][K] bf16 --------------
__global__ void transpose_w_kernel(const float* __restrict__ W, __nv_bfloat16* __restrict__ Wt, int K) {
    __shared__ float t[32][33];
    int bx = blockIdx.x * 32;   // n base
    int by = blockIdx.y * 32;   // k base
    int x = threadIdx.x, y = threadIdx.y;
    for (int yy = y; yy < 32; yy += 8)
        t[yy][x] = W[(size_t)(by + yy) * INNER + bx + x];
    __syncthreads();
    for (int yy = y; yy < 32; yy += 8)
        Wt[(size_t)(bx + yy) * K + by + x] = __float2bfloat16_rn(t[x][yy]);
}

// ---------------- projection GEMM (mma.sync, cp.async pipeline) -------------
// C[128x128] tile = A[128xK] * Wt[128 n-rows x K]^T, bf16 in / fp32 acc.
// K staged in 64-elem chunks (128B SW128-swizzled rows), NST=3 ring.
// 8 warps as 4(m) x 2(n): warp tile 32x64 (each warp owns one full head group).
// Epilogue: bias + per-head l2norm + bf16 store to [b][h][i][d].
#define NST 3
#define A_BYTES    16384                     // 128 rows x 128B
#define B_BYTES    16384
#define STAGE_BYTES (A_BYTES + B_BYTES)

__global__ __launch_bounds__(256, 2)
void proj_mma_kernel(const __nv_bfloat16* __restrict__ A, const __nv_bfloat16* __restrict__ Bt,
                     const float* __restrict__ bias, int K, int rowsPerB, int isSeq)
{
    extern __shared__ char dsm[];
    const int tid  = threadIdx.x;
    const int lane = tid & 31;
    const int w    = tid >> 5;
    const int wm   = w & 3;
    const int wn   = w >> 2;
    const int rowBase = blockIdx.y * 128;
    const int colBase = blockIdx.x * 128;
    const uint32_t dbase = (sptr(dsm) + 127u) & ~127u;
    const int KT = K >> 6;

    const __nv_bfloat16* Abase = A + (size_t)rowBase * K;
    const __nv_bfloat16* Bbase = Bt + (size_t)colBase * K;

    // stage loader: 1024 16B chunks for A, 1024 for B; SW128 xor swizzle
    auto load_stage = [&](int s, int buf) {
        const __nv_bfloat16* Ap = Abase + s * 64;
        uint32_t sa = dbase + buf * STAGE_BYTES;
#pragma unroll
        for (int q = 0; q < 4; q++) {
            int idx = tid + q * 256;
            int r = idx >> 3, c = idx & 7;
            cp_async16(sa + r * 128 + ((c ^ (r & 7)) << 4), Ap + (size_t)r * K + c * 8);
        }
        const __nv_bfloat16* Bp = Bbase + s * 64;
        uint32_t sb = dbase + buf * STAGE_BYTES + A_BYTES;
#pragma unroll
        for (int q = 0; q < 4; q++) {
            int idx = tid + q * 256;
            int r = idx >> 3, c = idx & 7;
            cp_async16(sb + r * 128 + ((c ^ (r & 7)) << 4), Bp + (size_t)r * K + c * 8);
        }
        CP_COMMIT();
    };

    float acc[2][8][4];
#pragma unroll
    for (int mi = 0; mi < 2; mi++)
#pragma unroll
        for (int ni = 0; ni < 8; ni++)
#pragma unroll
            for (int q = 0; q < 4; q++) acc[mi][ni][q] = 0.f;

    load_stage(0, 0);
    load_stage(1, 1);

    for (int kt = 0; kt < KT; kt++) {
        const int buf = kt % NST;
        asm volatile("cp.async.wait_group %0;\n" :: "n"(1) : "memory");
        __syncthreads();                       // stage kt visible; prev compute done
        if (kt + 2 < KT) load_stage(kt + 2, (kt + 2) % NST);
        else             CP_COMMIT();          // keep group count uniform

        const uint32_t sa = dbase + buf * STAGE_BYTES;
        const uint32_t sb = sa + A_BYTES;
#pragma unroll
        for (int ks = 0; ks < 4; ks++) {
            const int kchunk = ks * 2 + (lane >> 4);
            uint32_t af[2][4];
#pragma unroll
            for (int mi = 0; mi < 2; mi++) {
                int r = wm * 32 + mi * 16 + (lane & 15);
                ldsm_x4(af[mi], sa + r * 128 + ((kchunk ^ (r & 7)) << 4));
            }
            uint32_t bfr[8][2];
#pragma unroll
            for (int nb = 0; nb < 4; nb++) {
                int r = wn * 64 + nb * 16 + (lane & 15);
                uint32_t rr[4];
                ldsm_x4(rr, sb + r * 128 + ((kchunk ^ (r & 7)) << 4));
                bfr[2 * nb][0] = rr[0];     bfr[2 * nb][1] = rr[2];
                bfr[2 * nb + 1][0] = rr[1]; bfr[2 * nb + 1][1] = rr[3];
            }
#pragma unroll
            for (int mi = 0; mi < 2; mi++)
#pragma unroll
                for (int ni = 0; ni < 8; ni++) mma_bf16(acc[mi][ni], af[mi], bfr[ni]);
        }
    }

    // epilogue: bias + l2norm over this warp's 64-wide head group, store bf16
    __nv_bfloat16* __restrict__ out = isSeq ? g_seq_lat : g_aa_lat;
    const int h     = (colBase >> 6) + wn;
    const int bI    = rowBase / rowsPerB;            // 128 | rowsPerB -> no straddle
    const int iBase = rowBase - bI * rowsPerB;
    const float* bptr = bias + colBase + wn * 64;
#pragma unroll
    for (int mi = 0; mi < 2; mi++) {
        float slo = 0.f, shi = 0.f;
#pragma unroll
        for (int ni = 0; ni < 8; ni++) {
            int c0 = ni * 8 + 2 * (lane & 3);
            float b0 = bptr[c0], b1 = bptr[c0 + 1];
            acc[mi][ni][0] += b0; acc[mi][ni][1] += b1;
            acc[mi][ni][2] += b0; acc[mi][ni][3] += b1;
            slo += acc[mi][ni][0] * acc[mi][ni][0] + acc[mi][ni][1] * acc[mi][ni][1];
            shi += acc[mi][ni][2] * acc[mi][ni][2] + acc[mi][ni][3] * acc[mi][ni][3];
        }
        slo += __shfl_xor_sync(0xffffffffu, slo, 1);
        slo += __shfl_xor_sync(0xffffffffu, slo, 2);
        shi += __shfl_xor_sync(0xffffffffu, shi, 1);
        shi += __shfl_xor_sync(0xffffffffu, shi, 2);
        float scl = rsqrtf(fmaxf(slo, 1e-24f));
        float sch = rsqrtf(fmaxf(shi, 1e-24f));
        int rw = wm * 32 + mi * 16 + (lane >> 2);
        __nv_bfloat16* op = out + (((size_t)bI * HN + h) * rowsPerB + iBase + rw) * DD;
#pragma unroll
        for (int ni = 0; ni < 8; ni++) {
            int d = ni * 8 + 2 * (lane & 3);
            *(__nv_bfloat162*)(op + d) =
                __floats2bfloat162_rn(acc[mi][ni][0] * scl, acc[mi][ni][1] * scl);
            *(__nv_bfloat162*)(op + 8 * DD + d) =
                __floats2bfloat162_rn(acc[mi][ni][2] * sch, acc[mi][ni][3] * sch);
        }
    }
}

// ---------------- fused cosine-sim GEMM + masked sum-exp --------------------
__global__ __launch_bounds__(256) void sims_lse_kernel()
{
    const int bh = blockIdx.x;
    const int b = bh >> 5, h = bh & 31;
    const int it = blockIdx.y;
    const int tid = threadIdx.x, lane = tid & 31, w = tid >> 5;
    const int wm = w >> 2;
    const int wn = w & 3;

    __shared__ __nv_bfloat16 sQ[64][72];
    __shared__ __nv_bfloat16 sK[128][72];
    __shared__ float sMask[128];
    __shared__ float rowpart[4][64];
    __shared__ float rowacc[64];

    {
        const uint4* src = (const uint4*)(g_seq_lat + (((size_t)(b * HN + h)) * NN + it * 64) * DD);
        for (int i = tid; i < 512; i += 256) {
            int r = i >> 3, q = i & 7;
            *(uint4*)&sQ[r][q * 8] = src[i];
        }
    }
    if (tid < 64) rowacc[tid] = 0.f;
    __syncthreads();

    const __nv_bfloat16* kbase = g_aa_lat + ((size_t)(b * HN + h)) * MM * DD;
    for (int jc = 0; jc < 4; jc++) {
        const uint4* ksrc = (const uint4*)(kbase + (size_t)jc * 128 * DD);
        for (int i = tid; i < 1024; i += 256) {
            int r = i >> 3, q = i & 7;
            *(uint4*)&sK[r][q * 8] = ksrc[i];
        }
        if (tid < 128) sMask[tid] = g_maskf[b * MM + jc * 128 + tid];
        __syncthreads();

        float acc[2][4][4];
#pragma unroll
        for (int mi = 0; mi < 2; mi++)
#pragma unroll
            for (int ni = 0; ni < 4; ni++)
#pragma unroll
                for (int q = 0; q < 4; q++) acc[mi][ni][q] = 0.f;

#pragma unroll
        for (int ks = 0; ks < 4; ks++) {
            uint32_t af[2][4];
#pragma unroll
            for (int mi = 0; mi < 2; mi++)
                ldsm_x4(af[mi], sptr(&sQ[wm * 32 + mi * 16 + (lane & 15)][ks * 16 + ((lane >> 4) << 3)]));
            uint32_t bfr[4][2];
#pragma unroll
            for (int nb = 0; nb < 2; nb++) {
                uint32_t r[4];
                ldsm_x4(r, sptr(&sK[wn * 32 + nb * 16 + (lane & 15)][ks * 16 + ((lane >> 4) << 3)]));
                bfr[2 * nb][0] = r[0];     bfr[2 * nb][1] = r[2];
                bfr[2 * nb + 1][0] = r[1]; bfr[2 * nb + 1][1] = r[3];
            }
#pragma unroll
            for (int mi = 0; mi < 2; mi++)
#pragma unroll
                for (int ni = 0; ni < 4; ni++) mma_bf16(acc[mi][ni], af[mi], bfr[ni]);
        }

#pragma unroll
        for (int mi = 0; mi < 2; mi++) {
            float pl = 0.f, ph = 0.f;
#pragma unroll
            for (int ni = 0; ni < 4; ni++) {
                int c = wn * 32 + ni * 8 + 2 * (lane & 3);
                float m0 = sMask[c], m1 = sMask[c + 1];
                pl += __expf(acc[mi][ni][0]) * m0 + __expf(acc[mi][ni][1]) * m1;
                ph += __expf(acc[mi][ni][2]) * m0 + __expf(acc[mi][ni][3]) * m1;
            }
            pl += __shfl_xor_sync(0xffffffffu, pl, 1);
            pl += __shfl_xor_sync(0xffffffffu, pl, 2);
            ph += __shfl_xor_sync(0xffffffffu, ph, 1);
            ph += __shfl_xor_sync(0xffffffffu, ph, 2);
            if ((lane & 3) == 0) {
                int r = wm * 32 + mi * 16 + (lane >> 2);
                rowpart[wn][r] = pl;
                rowpart[wn][r + 8] = ph;
            }
        }
        __syncthreads();
        if (tid < 64)
            rowacc[tid] += rowpart[0][tid] + rowpart[1][tid] + rowpart[2][tid] + rowpart[3][tid];
        __syncthreads();
    }
    if (tid < 64) {
        int i = it * 64 + tid;
        g_lse[((size_t)b * NN + i) * HN + h] = logf(rowacc[tid]);
    }
}

// ---------------- gating -> collapsed mixing vector v[b][h] -----------------
__global__ void gating_kernel(const float* __restrict__ ctx, const float* __restrict__ ctx_w,
                              const float* __restrict__ ctx_b, const float* __restrict__ tw,
                              const float* __restrict__ pw)
{
    int b = blockIdx.x, t = threadIdx.x;
    __shared__ float sctx[CTXD];
    __shared__ float sgate[HN * HN];
    sctx[t] = ctx[b * CTXD + t];
    __syncthreads();
    for (int e = t; e < HN * HN; e += 256) {
        float s = ctx_b[e];
        for (int c = 0; c < CTXD; c++) s += sctx[c] * ctx_w[c * (HN * HN) + e];
        sgate[e] = 1.f / (1.f + __expf(-s));
    }
    __syncthreads();
    if (t < HN) {
        float v = 0.f;
#pragma unroll
        for (int e = 0; e < HN; e++) v += tw[t * HN + e] * sgate[t * HN + e] * pw[e];
        g_v[b * HN + t] = v;
    }
}

// ---------------- final: pred = softplus(lse . v + pred_b) ------------------
__global__ void pred_kernel(const float* __restrict__ pred_b, float* __restrict__ out)
{
    int idx = blockIdx.x * 256 + threadIdx.x;
    int b = idx / NN;
    const float4* p = (const float4*)&g_lse[(size_t)idx * HN];
    const float* v = &g_v[b * HN];
    float x = pred_b[0];
#pragma unroll
    for (int q = 0; q < 8; q++) {
        float4 l = p[q];
        x += l.x * v[4 * q] + l.y * v[4 * q + 1] + l.z * v[4 * q + 2] + l.w * v[4 * q + 3];
    }
    out[idx] = fmaxf(x, 0.f) + log1pf(__expf(-fabsf(x)));
}

// ---------------- launcher ---------------------------------------------------
extern "C" void kernel_launch(void* const* d_in, const int* in_sizes, int n_in,
                              void* d_out, int out_size)
{
    const float* seq_embed = (const float*)d_in[0];
    const float* aa_embed  = (const float*)d_in[1];
    const float* ctx       = (const float*)d_in[2];
    const float* seq_w     = (const float*)d_in[3];
    const float* seq_b     = (const float*)d_in[4];
    const float* aa_w      = (const float*)d_in[5];
    const float* aa_b      = (const float*)d_in[6];
    const float* tw        = (const float*)d_in[7];
    const float* ctx_w     = (const float*)d_in[8];
    const float* ctx_b     = (const float*)d_in[9];
    const float* pw        = (const float*)d_in[10];
    const float* pb        = (const float*)d_in[11];
    const unsigned char* mask = (const unsigned char*)d_in[12];
    float* out = (float*)d_out;

    const int dyn_smem = NST * STAGE_BYTES + 128;   // 96 KiB + align pad
    cudaFuncSetAttribute(proj_mma_kernel, cudaFuncAttributeMaxDynamicSharedMemorySize, dyn_smem);

    __nv_bfloat16* seq_bf; cudaGetSymbolAddress((void**)&seq_bf, g_seq_bf);
    __nv_bfloat16* aa_bf;  cudaGetSymbolAddress((void**)&aa_bf, g_aa_bf);
    __nv_bfloat16* wseq_t; cudaGetSymbolAddress((void**)&wseq_t, g_wseq_t);
    __nv_bfloat16* waa_t;  cudaGetSymbolAddress((void**)&waa_t, g_waa_t);

    mask_init_kernel<<<1, 256>>>(mask);
    {   // prepass conversions
        int n8s = (BB * NN * KSEQ) / 8;
        to_bf16_kernel<<<(n8s + 255) / 256, 256>>>(seq_embed, seq_bf, n8s);
        int n8a = (BB * MM * KAA) / 8;
        to_bf16_kernel<<<(n8a + 255) / 256, 256>>>(aa_embed, aa_bf, n8a);
        transpose_w_kernel<<<dim3(INNER / 32, KSEQ / 32), dim3(32, 8)>>>(seq_w, wseq_t, KSEQ);
        transpose_w_kernel<<<dim3(INNER / 32, KAA / 32), dim3(32, 8)>>>(aa_w, waa_t, KAA);
    }
    proj_mma_kernel<<<dim3(INNER / 128, (BB * NN) / 128), 256, dyn_smem>>>(seq_bf, wseq_t, seq_b, KSEQ, NN, 1);
    proj_mma_kernel<<<dim3(INNER / 128, (BB * MM) / 128), 256, dyn_smem>>>(aa_bf, waa_t, aa_b, KAA, MM, 0);
    sims_lse_kernel<<<dim3(BB * HN, NN / 64), 256>>>();
    gating_kernel<<<BB, 256>>>(ctx, ctx_w, ctx_b, tw, pw);
    pred_kernel<<<(BB * NN) / 256, 256>>>(pb, out);
}

// round 5
// speedup vs baseline: 3.4560x; 1.2691x over previous
#include <cuda_runtime.h>
#include <cuda_bf16.h>
#include <cstdint>

#define BB    8
#define NN    896
#define MM    512
#define KSEQ  3072
#define KAA   1280
#define HN    32
#define DD    64
#define INNER 2048
#define CTXD  256

// ---------------- scratch (no allocations allowed -> __device__ globals) ----
__device__ __nv_bfloat16 g_seq_lat[(size_t)BB * HN * NN * DD];   // 28 MiB
__device__ __nv_bfloat16 g_aa_lat[(size_t)BB * HN * MM * DD];    // 16 MiB
__device__ float g_lse[(size_t)BB * NN * HN];                    // [b][i][h]
__device__ float g_maskf[BB * MM];                               // 1 = keep, 0 = masked
__device__ float g_v[BB * HN];
// bf16 prepass buffers
__device__ __nv_bfloat16 g_seq_bf[(size_t)BB * NN * KSEQ];       // 44 MiB  [row][k]
__device__ __nv_bfloat16 g_aa_bf[(size_t)BB * MM * KAA];         // 10.5 MiB
__device__ __nv_bfloat16 g_wseq_t[(size_t)INNER * KSEQ];         // 12.6 MiB [col][k]
__device__ __nv_bfloat16 g_waa_t[(size_t)INNER * KAA];           // 5.2 MiB

// ---------------- PTX helpers -----------------------------------------------
__device__ __forceinline__ uint32_t sptr(const void* p) {
    return (uint32_t)__cvta_generic_to_shared(const_cast<void*>(p));
}
__device__ __forceinline__ void ldsm_x4(uint32_t* r, uint32_t addr) {
    asm volatile("ldmatrix.sync.aligned.m8n8.x4.shared.b16 {%0,%1,%2,%3}, [%4];\n"
                 : "=r"(r[0]), "=r"(r[1]), "=r"(r[2]), "=r"(r[3]) : "r"(addr));
}
__device__ __forceinline__ void mma_bf16(float* c, const uint32_t* a, const uint32_t* b) {
    asm volatile(
        "mma.sync.aligned.m16n8k16.row.col.f32.bf16.bf16.f32 "
        "{%0,%1,%2,%3}, {%4,%5,%6,%7}, {%8,%9}, {%0,%1,%2,%3};\n"
        : "+f"(c[0]), "+f"(c[1]), "+f"(c[2]), "+f"(c[3])
        : "r"(a[0]), "r"(a[1]), "r"(a[2]), "r"(a[3]), "r"(b[0]), "r"(b[1]));
}
__device__ __forceinline__ void cp_async16(uint32_t dst, const void* src) {
    asm volatile("cp.async.cg.shared.global [%0], [%1], 16;\n" :: "r"(dst), "l"(src));
}
#define CP_COMMIT()  asm volatile("cp.async.commit_group;\n" ::: "memory")

// ---------------- mask dtype detection + float expansion --------------------
__global__ void mask_init_kernel(const unsigned char* __restrict__ mraw) {
    __shared__ int u8f, f32f;
    if (threadIdx.x == 0) { u8f = 0; f32f = 0; }
    __syncthreads();
    for (int i = threadIdx.x; i < BB * MM; i += blockDim.x) {
        unsigned char v = mraw[i];
        if ((i & 3) != 0 && v != 0) atomicOr(&u8f, 1);
        if ((i & 3) == 3 && v == 0x3f) atomicOr(&f32f, 1);
    }
    __syncthreads();
    int mode = f32f ? 2 : (u8f ? 0 : 1);
    for (int i = threadIdx.x; i < BB * MM; i += blockDim.x) {
        bool msk;
        if (mode == 0)      msk = mraw[i] != 0;
        else if (mode == 1) msk = ((const int*)mraw)[i] != 0;
        else                msk = ((const float*)mraw)[i] != 0.0f;
        g_maskf[i] = msk ? 0.0f : 1.0f;
    }
}

// ---------------- prepass: fp32 -> bf16 elementwise -------------------------
__global__ void to_bf16_kernel(const float* __restrict__ in, __nv_bfloat16* __restrict__ out, int n8) {
    int i = blockIdx.x * 256 + threadIdx.x;
    if (i >= n8) return;
    float4 a = ((const float4*)in)[2 * i];
    float4 b = ((const float4*)in)[2 * i + 1];
    __nv_bfloat162 o[4];
    o[0] = __floats2bfloat162_rn(a.x, a.y);
    o[1] = __floats2bfloat162_rn(a.z, a.w);
    o[2] = __floats2bfloat162_rn(b.x, b.y);
    o[3] = __floats2bfloat162_rn(b.z, b.w);
    ((uint4*)out)[i] = *(uint4*)o;
}

// ---------------- prepass: W[K][2048] fp32 -> Wt[2048][K] bf16 --------------
__global__ void transpose_w_kernel(const float* __restrict__ W, __nv_bfloat16* __restrict__ Wt, int K) {
    __shared__ float t[32][33];
    int bx = blockIdx.x * 32;   // n base
    int by = blockIdx.y * 32;   // k base
    int x = threadIdx.x, y = threadIdx.y;
    for (int yy = y; yy < 32; yy += 8)
        t[yy][x] = W[(size_t)(by + yy) * INNER + bx + x];
    __syncthreads();
    for (int yy = y; yy < 32; yy += 8)
        Wt[(size_t)(bx + yy) * K + by + x] = __float2bfloat16_rn(t[x][yy]);
}

// ---------------- projection GEMM (mma.sync, cp.async pipeline) -------------
#define NST 3
#define A_BYTES    16384                     // 128 rows x 128B
#define B_BYTES    16384
#define STAGE_BYTES (A_BYTES + B_BYTES)

__global__ __launch_bounds__(256, 2)
void proj_mma_kernel(const __nv_bfloat16* __restrict__ A, const __nv_bfloat16* __restrict__ Bt,
                     const float* __restrict__ bias, int K, int rowsPerB, int isSeq)
{
    extern __shared__ char dsm[];
    const int tid  = threadIdx.x;
    const int lane = tid & 31;
    const int w    = tid >> 5;
    const int wm   = w & 3;
    const int wn   = w >> 2;
    const int rowBase = blockIdx.y * 128;
    const int colBase = blockIdx.x * 128;
    const uint32_t dbase = (sptr(dsm) + 127u) & ~127u;
    const int KT = K >> 6;

    const __nv_bfloat16* Abase = A + (size_t)rowBase * K;
    const __nv_bfloat16* Bbase = Bt + (size_t)colBase * K;

    auto load_stage = [&](int s, int buf) {
        const __nv_bfloat16* Ap = Abase + s * 64;
        uint32_t sa = dbase + buf * STAGE_BYTES;
#pragma unroll
        for (int q = 0; q < 4; q++) {
            int idx = tid + q * 256;
            int r = idx >> 3, c = idx & 7;
            cp_async16(sa + r * 128 + ((c ^ (r & 7)) << 4), Ap + (size_t)r * K + c * 8);
        }
        const __nv_bfloat16* Bp = Bbase + s * 64;
        uint32_t sb = dbase + buf * STAGE_BYTES + A_BYTES;
#pragma unroll
        for (int q = 0; q < 4; q++) {
            int idx = tid + q * 256;
            int r = idx >> 3, c = idx & 7;
            cp_async16(sb + r * 128 + ((c ^ (r & 7)) << 4), Bp + (size_t)r * K + c * 8);
        }
        CP_COMMIT();
    };

    float acc[2][8][4];
#pragma unroll
    for (int mi = 0; mi < 2; mi++)
#pragma unroll
        for (int ni = 0; ni < 8; ni++)
#pragma unroll
            for (int q = 0; q < 4; q++) acc[mi][ni][q] = 0.f;

    load_stage(0, 0);
    load_stage(1, 1);

    for (int kt = 0; kt < KT; kt++) {
        const int buf = kt % NST;
        asm volatile("cp.async.wait_group %0;\n" :: "n"(1) : "memory");
        __syncthreads();
        if (kt + 2 < KT) load_stage(kt + 2, (kt + 2) % NST);
        else             CP_COMMIT();

        const uint32_t sa = dbase + buf * STAGE_BYTES;
        const uint32_t sb = sa + A_BYTES;
#pragma unroll
        for (int ks = 0; ks < 4; ks++) {
            const int kchunk = ks * 2 + (lane >> 4);
            uint32_t af[2][4];
#pragma unroll
            for (int mi = 0; mi < 2; mi++) {
                int r = wm * 32 + mi * 16 + (lane & 15);
                ldsm_x4(af[mi], sa + r * 128 + ((kchunk ^ (r & 7)) << 4));
            }
            uint32_t bfr[8][2];
#pragma unroll
            for (int nb = 0; nb < 4; nb++) {
                int r = wn * 64 + nb * 16 + (lane & 15);
                uint32_t rr[4];
                ldsm_x4(rr, sb + r * 128 + ((kchunk ^ (r & 7)) << 4));
                bfr[2 * nb][0] = rr[0];     bfr[2 * nb][1] = rr[2];
                bfr[2 * nb + 1][0] = rr[1]; bfr[2 * nb + 1][1] = rr[3];
            }
#pragma unroll
            for (int mi = 0; mi < 2; mi++)
#pragma unroll
                for (int ni = 0; ni < 8; ni++) mma_bf16(acc[mi][ni], af[mi], bfr[ni]);
        }
    }

    __nv_bfloat16* __restrict__ out = isSeq ? g_seq_lat : g_aa_lat;
    const int h     = (colBase >> 6) + wn;
    const int bI    = rowBase / rowsPerB;
    const int iBase = rowBase - bI * rowsPerB;
    const float* bptr = bias + colBase + wn * 64;
#pragma unroll
    for (int mi = 0; mi < 2; mi++) {
        float slo = 0.f, shi = 0.f;
#pragma unroll
        for (int ni = 0; ni < 8; ni++) {
            int c0 = ni * 8 + 2 * (lane & 3);
            float b0 = bptr[c0], b1 = bptr[c0 + 1];
            acc[mi][ni][0] += b0; acc[mi][ni][1] += b1;
            acc[mi][ni][2] += b0; acc[mi][ni][3] += b1;
            slo += acc[mi][ni][0] * acc[mi][ni][0] + acc[mi][ni][1] * acc[mi][ni][1];
            shi += acc[mi][ni][2] * acc[mi][ni][2] + acc[mi][ni][3] * acc[mi][ni][3];
        }
        slo += __shfl_xor_sync(0xffffffffu, slo, 1);
        slo += __shfl_xor_sync(0xffffffffu, slo, 2);
        shi += __shfl_xor_sync(0xffffffffu, shi, 1);
        shi += __shfl_xor_sync(0xffffffffu, shi, 2);
        float scl = rsqrtf(fmaxf(slo, 1e-24f));
        float sch = rsqrtf(fmaxf(shi, 1e-24f));
        int rw = wm * 32 + mi * 16 + (lane >> 2);
        __nv_bfloat16* op = out + (((size_t)bI * HN + h) * rowsPerB + iBase + rw) * DD;
#pragma unroll
        for (int ni = 0; ni < 8; ni++) {
            int d = ni * 8 + 2 * (lane & 3);
            *(__nv_bfloat162*)(op + d) =
                __floats2bfloat162_rn(acc[mi][ni][0] * scl, acc[mi][ni][1] * scl);
            *(__nv_bfloat162*)(op + 8 * DD + d) =
                __floats2bfloat162_rn(acc[mi][ni][2] * sch, acc[mi][ni][3] * sch);
        }
    }
}

// ---------------- fused cosine-sim GEMM + masked sum-exp --------------------
// Per (b,h): tile 128 i-rows x 128 j-chunk, 3-stage cp.async K ring, warp tile
// 32x64 (4m x 2n warps). sims in [-1,1] -> sum exp directly, no max pass.
#define SQ_BYTES   16384                    // 128 x 128B
#define SK_BYTES   16384
#define SIM_SMEM   (SQ_BYTES + 3 * SK_BYTES + 2048 + 1024 + 512 + 128)

__global__ __launch_bounds__(256, 2) void sims_lse_kernel()
{
    extern __shared__ char dsm[];
    const int bh = blockIdx.x;
    const int b = bh >> 5, h = bh & 31;
    const int it = blockIdx.y;
    const int tid = threadIdx.x, lane = tid & 31, w = tid >> 5;
    const int wm = w & 3;     // 0..3 (m)
    const int wn = w >> 2;    // 0..1 (n)

    const uint32_t base   = (sptr(dsm) + 127u) & ~127u;
    const uint32_t sQ     = base;
    const uint32_t sK     = base + SQ_BYTES;            // 3 bufs
    const uint32_t sMaskA = base + SQ_BYTES + 3 * SK_BYTES;
    float* maskAll = (float*)(dsm + (sMaskA - sptr(dsm)));
    float* rowpart = (float*)(dsm + (sMaskA - sptr(dsm)) + 2048);   // [2][128]
    float* rowacc  = rowpart + 256;                                  // [128]

    const __nv_bfloat16* qsrc = g_seq_lat + (((size_t)(b * HN + h)) * NN + it * 128) * DD;
    const __nv_bfloat16* kbase = g_aa_lat + ((size_t)(b * HN + h)) * MM * DD;

    auto load_k = [&](int jc, int buf) {
        const __nv_bfloat16* Kp = kbase + (size_t)jc * 128 * DD;
        uint32_t sb = sK + buf * SK_BYTES;
#pragma unroll
        for (int q = 0; q < 4; q++) {
            int idx = tid + q * 256;
            int r = idx >> 3, c = idx & 7;
            cp_async16(sb + r * 128 + ((c ^ (r & 7)) << 4), Kp + (size_t)r * DD + c * 8);
        }
        CP_COMMIT();
    };

    // prologue: Q + mask + K0 (group 0), K1 (group 1)
    {
#pragma unroll
        for (int q = 0; q < 4; q++) {
            int idx = tid + q * 256;
            int r = idx >> 3, c = idx & 7;
            cp_async16(sQ + r * 128 + ((c ^ (r & 7)) << 4), qsrc + (size_t)r * DD + c * 8);
        }
        if (tid < 128) cp_async16(sMaskA + tid * 16, &g_maskf[b * MM + tid * 4]);
        const __nv_bfloat16* Kp = kbase;
#pragma unroll
        for (int q = 0; q < 4; q++) {
            int idx = tid + q * 256;
            int r = idx >> 3, c = idx & 7;
            cp_async16(sK + r * 128 + ((c ^ (r & 7)) << 4), Kp + (size_t)r * DD + c * 8);
        }
        CP_COMMIT();
    }
    load_k(1, 1);
    if (tid < 128) rowacc[tid] = 0.f;

    for (int jc = 0; jc < 4; jc++) {
        const int buf = jc % 3;
        asm volatile("cp.async.wait_group %0;\n" :: "n"(1) : "memory");
        __syncthreads();
        if (jc + 2 < 4) load_k(jc + 2, (jc + 2) % 3);
        else            CP_COMMIT();

        float acc[2][8][4];
#pragma unroll
        for (int mi = 0; mi < 2; mi++)
#pragma unroll
            for (int ni = 0; ni < 8; ni++)
#pragma unroll
                for (int q = 0; q < 4; q++) acc[mi][ni][q] = 0.f;

        const uint32_t sb = sK + buf * SK_BYTES;
#pragma unroll
        for (int ks = 0; ks < 4; ks++) {
            const int kchunk = ks * 2 + (lane >> 4);
            uint32_t af[2][4];
#pragma unroll
            for (int mi = 0; mi < 2; mi++) {
                int r = wm * 32 + mi * 16 + (lane & 15);
                ldsm_x4(af[mi], sQ + r * 128 + ((kchunk ^ (r & 7)) << 4));
            }
            uint32_t bfr[8][2];
#pragma unroll
            for (int nb = 0; nb < 4; nb++) {
                int r = wn * 64 + nb * 16 + (lane & 15);
                uint32_t rr[4];
                ldsm_x4(rr, sb + r * 128 + ((kchunk ^ (r & 7)) << 4));
                bfr[2 * nb][0] = rr[0];     bfr[2 * nb][1] = rr[2];
                bfr[2 * nb + 1][0] = rr[1]; bfr[2 * nb + 1][1] = rr[3];
            }
#pragma unroll
            for (int mi = 0; mi < 2; mi++)
#pragma unroll
                for (int ni = 0; ni < 8; ni++) mma_bf16(acc[mi][ni], af[mi], bfr[ni]);
        }

        // exp + mask + per-row partial sums over this warp's 64 cols
        const float* mp = maskAll + jc * 128 + wn * 64;
#pragma unroll
        for (int mi = 0; mi < 2; mi++) {
            float pl = 0.f, ph = 0.f;
#pragma unroll
            for (int ni = 0; ni < 8; ni++) {
                int c = ni * 8 + 2 * (lane & 3);
                float m0 = mp[c], m1 = mp[c + 1];
                pl += __expf(acc[mi][ni][0]) * m0 + __expf(acc[mi][ni][1]) * m1;
                ph += __expf(acc[mi][ni][2]) * m0 + __expf(acc[mi][ni][3]) * m1;
            }
            pl += __shfl_xor_sync(0xffffffffu, pl, 1);
            pl += __shfl_xor_sync(0xffffffffu, pl, 2);
            ph += __shfl_xor_sync(0xffffffffu, ph, 1);
            ph += __shfl_xor_sync(0xffffffffu, ph, 2);
            if ((lane & 3) == 0) {
                int r = wm * 32 + mi * 16 + (lane >> 2);
                rowpart[wn * 128 + r] = pl;
                rowpart[wn * 128 + r + 8] = ph;
            }
        }
        __syncthreads();
        if (tid < 128) rowacc[tid] += rowpart[tid] + rowpart[128 + tid];
    }
    __syncthreads();
    if (tid < 128) {
        int i = it * 128 + tid;
        g_lse[((size_t)b * NN + i) * HN + h] = logf(rowacc[tid]);
    }
}

// ---------------- gating -> collapsed mixing vector v[b][h] -----------------
__global__ void gating_kernel(const float* __restrict__ ctx, const float* __restrict__ ctx_w,
                              const float* __restrict__ ctx_b, const float* __restrict__ tw,
                              const float* __restrict__ pw)
{
    int b = blockIdx.x, t = threadIdx.x;
    __shared__ float sctx[CTXD];
    __shared__ float sgate[HN * HN];
    sctx[t] = ctx[b * CTXD + t];
    __syncthreads();
    for (int e = t; e < HN * HN; e += 256) {
        float s = ctx_b[e];
        for (int c = 0; c < CTXD; c++) s += sctx[c] * ctx_w[c * (HN * HN) + e];
        sgate[e] = 1.f / (1.f + __expf(-s));
    }
    __syncthreads();
    if (t < HN) {
        float v = 0.f;
#pragma unroll
        for (int e = 0; e < HN; e++) v += tw[t * HN + e] * sgate[t * HN + e] * pw[e];
        g_v[b * HN + t] = v;
    }
}

// ---------------- final: pred = softplus(lse . v + pred_b) ------------------
__global__ void pred_kernel(const float* __restrict__ pred_b, float* __restrict__ out)
{
    int idx = blockIdx.x * 256 + threadIdx.x;
    int b = idx / NN;
    const float4* p = (const float4*)&g_lse[(size_t)idx * HN];
    const float* v = &g_v[b * HN];
    float x = pred_b[0];
#pragma unroll
    for (int q = 0; q < 8; q++) {
        float4 l = p[q];
        x += l.x * v[4 * q] + l.y * v[4 * q + 1] + l.z * v[4 * q + 2] + l.w * v[4 * q + 3];
    }
    out[idx] = fmaxf(x, 0.f) + log1pf(__expf(-fabsf(x)));
}

// ---------------- launcher (fork-join streams for prepass overlap) ----------
extern "C" void kernel_launch(void* const* d_in, const int* in_sizes, int n_in,
                              void* d_out, int out_size)
{
    const float* seq_embed = (const float*)d_in[0];
    const float* aa_embed  = (const float*)d_in[1];
    const float* ctx       = (const float*)d_in[2];
    const float* seq_w     = (const float*)d_in[3];
    const float* seq_b     = (const float*)d_in[4];
    const float* aa_w      = (const float*)d_in[5];
    const float* aa_b      = (const float*)d_in[6];
    const float* tw        = (const float*)d_in[7];
    const float* ctx_w     = (const float*)d_in[8];
    const float* ctx_b     = (const float*)d_in[9];
    const float* pw        = (const float*)d_in[10];
    const float* pb        = (const float*)d_in[11];
    const unsigned char* mask = (const unsigned char*)d_in[12];
    float* out = (float*)d_out;

    const int dyn_smem = NST * STAGE_BYTES + 128;
    cudaFuncSetAttribute(proj_mma_kernel, cudaFuncAttributeMaxDynamicSharedMemorySize, dyn_smem);
    cudaFuncSetAttribute(sims_lse_kernel, cudaFuncAttributeMaxDynamicSharedMemorySize, SIM_SMEM);

    __nv_bfloat16* seq_bf; cudaGetSymbolAddress((void**)&seq_bf, g_seq_bf);
    __nv_bfloat16* aa_bf;  cudaGetSymbolAddress((void**)&aa_bf, g_aa_bf);
    __nv_bfloat16* wseq_t; cudaGetSymbolAddress((void**)&wseq_t, g_wseq_t);
    __nv_bfloat16* waa_t;  cudaGetSymbolAddress((void**)&waa_t, g_waa_t);

    cudaStream_t s1, s2;
    cudaStreamCreateWithFlags(&s1, cudaStreamNonBlocking);
    cudaStreamCreateWithFlags(&s2, cudaStreamNonBlocking);
    cudaEvent_t eRoot, eAA, eWT;
    cudaEventCreateWithFlags(&eRoot, cudaEventDisableTiming);
    cudaEventCreateWithFlags(&eAA, cudaEventDisableTiming);
    cudaEventCreateWithFlags(&eWT, cudaEventDisableTiming);

    cudaEventRecord(eRoot, 0);
    cudaStreamWaitEvent(s1, eRoot, 0);
    cudaStreamWaitEvent(s2, eRoot, 0);

    // s1: mask + gating + full aa chain (hidden under proj_seq)
    mask_init_kernel<<<1, 256, 0, s1>>>(mask);
    gating_kernel<<<BB, 256, 0, s1>>>(ctx, ctx_w, ctx_b, tw, pw);
    {
        int n8a = (BB * MM * KAA) / 8;
        to_bf16_kernel<<<(n8a + 255) / 256, 256, 0, s1>>>(aa_embed, aa_bf, n8a);
        transpose_w_kernel<<<dim3(INNER / 32, KAA / 32), dim3(32, 8), 0, s1>>>(aa_w, waa_t, KAA);
    }
    proj_mma_kernel<<<dim3(INNER / 128, (BB * MM) / 128), 256, dyn_smem, s1>>>(aa_bf, waa_t, aa_b, KAA, MM, 0);
    cudaEventRecord(eAA, s1);

    // s2: seq weight transpose, parallel with s0's activation convert
    transpose_w_kernel<<<dim3(INNER / 32, KSEQ / 32), dim3(32, 8), 0, s2>>>(seq_w, wseq_t, KSEQ);
    cudaEventRecord(eWT, s2);

    // s0 (default): seq chain -> join -> sims -> pred
    {
        int n8s = (BB * NN * KSEQ) / 8;
        to_bf16_kernel<<<(n8s + 255) / 256, 256>>>(seq_embed, seq_bf, n8s);
    }
    cudaStreamWaitEvent(0, eWT, 0);
    proj_mma_kernel<<<dim3(INNER / 128, (BB * NN) / 128), 256, dyn_smem>>>(seq_bf, wseq_t, seq_b, KSEQ, NN, 1);
    cudaStreamWaitEvent(0, eAA, 0);
    sims_lse_kernel<<<dim3(BB * HN, NN / 128), 256, SIM_SMEM>>>();
    pred_kernel<<<(BB * NN) / 256, 256>>>(pb, out);

    cudaEventDestroy(eRoot);
    cudaEventDestroy(eAA);
    cudaEventDestroy(eWT);
    cudaStreamDestroy(s1);
    cudaStreamDestroy(s2);
}